// round 3
// baseline (speedup 1.0000x reference)
#include <cuda_runtime.h>
#include <math.h>
#include <cstdint>

// Problem sizes
#define Bv 256
#define Tv 512
#define Fv 512
#define Hv 512
#define FH 2048
#define NSTEPS 257   // layer1 steps 0..255; layer2 pipelined (batch b = s-1) steps 1..256

// ---------------- device scratch (no allocations allowed) ----------------
__device__ __align__(16) float gZ1[Bv * FH];     // x[:,T-1,:] @ Wi1 + b1
__device__ __align__(16) float gH1buf[2][Hv];    // ping-pong layer1 hidden
__device__ __align__(16) float gH2buf[2][Hv];    // ping-pong layer2 hidden
__device__ __align__(16) float gC1[Hv];          // layer1 cell state
__device__ __align__(16) float gC2[Hv];          // layer2 cell state
__device__ __align__(16) float gH2all[Bv * Hv];  // all layer2 outputs ("last" matrix)

__device__ __forceinline__ float sigf(float x) { return 1.0f / (1.0f + expf(-x)); }

// ---------------- init (fresh state every launch/replay) ----------------
__global__ void initK() {
    int t = threadIdx.x;
    for (int i = t; i < Hv; i += blockDim.x) {
        gH1buf[0][i] = 0.f; gH1buf[1][i] = 0.f;
        gH2buf[0][i] = 0.f; gH2buf[1][i] = 0.f;
        gC1[i] = 0.f;       gC2[i] = 0.f;
    }
}

// ---------------- Phase A: Z1 = x[:,T-1,:] @ Wi1 + b1 ----------------
// grid (2, 32): bx = col-half (1024 cols), by = row group of 8 batches.
// 256 threads; thread owns 4 consecutive cols for all 8 rows.
__global__ void gemmZ1(const float* __restrict__ x,
                       const float* __restrict__ Wi1,
                       const float* __restrict__ b1) {
    __shared__ __align__(16) float xs[8][512];
    const int tid = threadIdx.x;
    const int col = blockIdx.x * 1024 + tid * 4;
    const int b0  = blockIdx.y * 8;

    // stage 8 x-rows (at t = T-1)
    for (int i = tid; i < 8 * 512; i += 256) {
        int r = i >> 9, f = i & 511;
        xs[r][f] = x[(size_t)(b0 + r) * Tv * Fv + (size_t)(Tv - 1) * Fv + f];
    }
    __syncthreads();

    float4 acc[8];
    float4 bv = *(const float4*)(b1 + col);
    #pragma unroll
    for (int r = 0; r < 8; r++) acc[r] = bv;

    for (int k = 0; k < Fv; k++) {
        float4 w = *(const float4*)(Wi1 + (size_t)k * FH + col);
        #pragma unroll
        for (int r = 0; r < 8; r++) {
            float xv = xs[r][k];
            acc[r].x = fmaf(xv, w.x, acc[r].x);
            acc[r].y = fmaf(xv, w.y, acc[r].y);
            acc[r].z = fmaf(xv, w.z, acc[r].z);
            acc[r].w = fmaf(xv, w.w, acc[r].w);
        }
    }
    #pragma unroll
    for (int r = 0; r < 8; r++)
        *(float4*)&gZ1[(size_t)(b0 + r) * FH + col] = acc[r];
}

// ---------------- Phase B: one kernel per recurrence step ----------------
// grid 96 x 256 threads.
//   Blocks 0..31  : layer1. Block owns 16 units (64 gate-cols). Active for s < 256.
//       z = gZ1[s] + h1prev @ Wh1 ; update c1, h1.
//   Blocks 32..95 : layer2. Block owns 8 units (32 gate-cols). Active for s >= 1.
//       z = h1[s-1] @ Wi2 + b2 + h2prev @ Wh2 ; update c2, h2; record gH2all[s-1].
// Kernel boundary = grid barrier. All weight reads coalesced float4.
__global__ void stepK(const float* __restrict__ Wh1, const float* __restrict__ Wi2,
                      const float* __restrict__ Wh2, const float* __restrict__ b2,
                      int s) {
    __shared__ __align__(16) float sH[1024];
    __shared__ __align__(16) float sPart[1024];
    __shared__ float sZ[64];

    const int tid = threadIdx.x;
    const int bx  = blockIdx.x;
    const int rb  = s & 1, wb = rb ^ 1;

    if (bx < 32) {
        // ---------- layer 1 ----------
        if (s >= Bv) return;
        const int u0 = bx * 16;

        for (int i = tid; i < Hv; i += 256) sH[i] = gH1buf[rb][i];
        __syncthreads();

        const int cg = tid & 15;          // col group (4 cols), local cols c0..c0+3
        const int ks = tid >> 4;          // 16 k-slices of 32
        const int c0 = cg * 4;
        const int g  = c0 >> 4;           // gate (16 cols per gate)
        const int col = g * Hv + u0 + (c0 & 15);
        const int kb  = ks * 32;

        const float* Wp = Wh1 + (size_t)kb * FH + col;
        float4 a = make_float4(0.f, 0.f, 0.f, 0.f);
        #pragma unroll 8
        for (int j = 0; j < 32; j++) {
            float4 w = *(const float4*)(Wp + (size_t)j * FH);
            float hk = sH[kb + j];
            a.x = fmaf(hk, w.x, a.x); a.y = fmaf(hk, w.y, a.y);
            a.z = fmaf(hk, w.z, a.z); a.w = fmaf(hk, w.w, a.w);
        }
        *(float4*)&sPart[ks * 64 + c0] = a;
        __syncthreads();

        if (tid < 64) {
            float z = 0.f;
            #pragma unroll
            for (int r = 0; r < 16; r++) z += sPart[r * 64 + tid];
            const int gg = tid >> 4;
            const int cc = gg * Hv + u0 + (tid & 15);
            sZ[tid] = z + gZ1[(size_t)s * FH + cc];
        }
        __syncthreads();

        if (tid < 16) {
            const int u = u0 + tid;
            float zi = sZ[tid], zf = sZ[16 + tid], zg = sZ[32 + tid], zo = sZ[48 + tid];
            float c = sigf(zf) * gC1[u] + sigf(zi) * tanhf(zg);
            gC1[u] = c;
            gH1buf[wb][u] = sigf(zo) * tanhf(c);
        }
    } else {
        // ---------- layer 2 ----------
        if (s < 1) return;
        const int lb = bx - 32;           // 0..63
        const int u0 = lb * 8;

        for (int i = tid; i < Hv; i += 256) sH[i]       = gH1buf[rb][i];   // input h1[s-1]
        for (int i = tid; i < Hv; i += 256) sH[Hv + i]  = gH2buf[rb][i];   // carry h2[s-2]
        __syncthreads();

        const int cg = tid & 7;           // 8 col groups (4 cols) -> 32 cols
        const int ks = tid >> 3;          // 32 k-slices of 32 (k total 1024)
        const int c0 = cg * 4;
        const int g  = c0 >> 3;           // gate (8 cols per gate)
        const int col = g * Hv + u0 + (c0 & 7);
        const int kb  = ks * 32;

        const float* Wp = (kb < Hv ? Wi2 + (size_t)kb * FH
                                   : Wh2 + (size_t)(kb - Hv) * FH) + col;
        float4 a = make_float4(0.f, 0.f, 0.f, 0.f);
        #pragma unroll 8
        for (int j = 0; j < 32; j++) {
            float4 w = *(const float4*)(Wp + (size_t)j * FH);
            float hk = sH[kb + j];
            a.x = fmaf(hk, w.x, a.x); a.y = fmaf(hk, w.y, a.y);
            a.z = fmaf(hk, w.z, a.z); a.w = fmaf(hk, w.w, a.w);
        }
        *(float4*)&sPart[ks * 32 + c0] = a;
        __syncthreads();

        if (tid < 32) {
            float z = 0.f;
            #pragma unroll
            for (int r = 0; r < 32; r++) z += sPart[r * 32 + tid];
            const int gg = tid >> 3;
            const int cc = gg * Hv + u0 + (tid & 7);
            sZ[tid] = z + b2[cc];
        }
        __syncthreads();

        if (tid < 8) {
            const int u = u0 + tid;
            float zi = sZ[tid], zf = sZ[8 + tid], zg = sZ[16 + tid], zo = sZ[24 + tid];
            float c = sigf(zf) * gC2[u] + sigf(zi) * tanhf(zg);
            gC2[u] = c;
            float h = sigf(zo) * tanhf(c);
            gH2buf[wb][u] = h;
            gH2all[(size_t)(s - 1) * Hv + u] = h;
        }
    }
}

// ---------------- Phase C: out = H2all @ Wd + bd ----------------
__global__ void outK(const float* __restrict__ Wd, const float* __restrict__ bd,
                     float* __restrict__ out) {
    const int m    = blockIdx.x;
    const int o    = threadIdx.y;
    const int lane = threadIdx.x;
    const float* h = gH2all + (size_t)m * Hv;
    float acc = 0.f;
    #pragma unroll
    for (int j = 0; j < 16; j++) {
        int k = lane * 16 + j;
        acc = fmaf(h[k], __ldg(Wd + (size_t)k * 10 + o), acc);
    }
    #pragma unroll
    for (int off = 16; off; off >>= 1)
        acc += __shfl_xor_sync(0xffffffffu, acc, off);
    if (lane == 0) out[m * 10 + o] = acc + __ldg(bd + o);
}

// ---------------- launch ----------------
extern "C" void kernel_launch(void* const* d_in, const int* in_sizes, int n_in,
                              void* d_out, int out_size) {
    (void)in_sizes; (void)n_in; (void)out_size;
    const float* x   = (const float*)d_in[0];
    const float* Wi1 = (const float*)d_in[1];
    const float* Wh1 = (const float*)d_in[2];
    const float* b1  = (const float*)d_in[3];
    const float* Wi2 = (const float*)d_in[4];
    const float* Wh2 = (const float*)d_in[5];
    const float* b2  = (const float*)d_in[6];
    const float* Wd  = (const float*)d_in[7];
    const float* bd  = (const float*)d_in[8];
    float* out = (float*)d_out;

    initK<<<1, 256>>>();
    gemmZ1<<<dim3(2, 32), 256>>>(x, Wi1, b1);
    for (int s = 0; s < NSTEPS; s++)
        stepK<<<96, 256>>>(Wh1, Wi2, Wh2, b2, s);
    outK<<<256, dim3(32, 10)>>>(Wd, bd, out);
}

// round 4
// speedup vs baseline: 1.1136x; 1.1136x over previous
#include <cuda_runtime.h>
#include <math.h>
#include <cstdint>

// Problem sizes
#define Bv 256
#define Tv 512
#define Fv 512
#define Hv 512
#define FH 2048
#define NSTEPS 257   // layer1 steps 0..255; layer2 pipelined (batch b = s-1) steps 1..256
#define GRIDB 96

// ---------------- device scratch (no allocations allowed) ----------------
__device__ __align__(16) float gZ1[Bv * FH];     // x[:,T-1,:] @ Wi1 + b1
__device__ __align__(16) float gH1buf[2][Hv];    // ping-pong layer1 hidden
__device__ __align__(16) float gH2buf[2][Hv];    // ping-pong layer2 hidden
__device__ __align__(16) float gC1[Hv];          // layer1 cell state
__device__ __align__(16) float gC2[Hv];          // layer2 cell state
__device__ __align__(16) float gH2all[Bv * Hv];  // all layer2 outputs ("last" matrix)
__device__ int g_cnt;                            // grid barrier counter (monotonic per launch)

__device__ __forceinline__ float sigf(float x) { return 1.0f / (1.0f + expf(-x)); }

__device__ __forceinline__ int ld_acq(const int* p) {
    int v;
    asm volatile("ld.acquire.gpu.global.b32 %0, [%1];" : "=r"(v) : "l"(p));
    return v;
}
__device__ __forceinline__ float ldcg(const float* p) {
    float v;
    asm volatile("ld.global.cg.f32 %0, [%1];" : "=f"(v) : "l"(p));
    return v;
}

// ---------------- init (fresh state every launch/replay) ----------------
__global__ void initK() {
    int t = threadIdx.x;
    for (int i = t; i < Hv; i += blockDim.x) {
        gH1buf[0][i] = 0.f; gH1buf[1][i] = 0.f;
        gH2buf[0][i] = 0.f; gH2buf[1][i] = 0.f;
        gC1[i] = 0.f;       gC2[i] = 0.f;
    }
    if (t == 0) g_cnt = 0;
}

// ---------------- Phase A: Z1 = x[:,T-1,:] @ Wi1 + b1 ----------------
__global__ void gemmZ1(const float* __restrict__ x,
                       const float* __restrict__ Wi1,
                       const float* __restrict__ b1) {
    __shared__ __align__(16) float xs[8][512];
    const int tid = threadIdx.x;
    const int col = blockIdx.x * 1024 + tid * 4;
    const int b0  = blockIdx.y * 8;

    for (int i = tid; i < 8 * 512; i += 256) {
        int r = i >> 9, f = i & 511;
        xs[r][f] = x[(size_t)(b0 + r) * Tv * Fv + (size_t)(Tv - 1) * Fv + f];
    }
    __syncthreads();

    float4 acc[8];
    float4 bv = *(const float4*)(b1 + col);
    #pragma unroll
    for (int r = 0; r < 8; r++) acc[r] = bv;

    for (int k = 0; k < Fv; k++) {
        float4 w = *(const float4*)(Wi1 + (size_t)k * FH + col);
        #pragma unroll
        for (int r = 0; r < 8; r++) {
            float xv = xs[r][k];
            acc[r].x = fmaf(xv, w.x, acc[r].x);
            acc[r].y = fmaf(xv, w.y, acc[r].y);
            acc[r].z = fmaf(xv, w.z, acc[r].z);
            acc[r].w = fmaf(xv, w.w, acc[r].w);
        }
    }
    #pragma unroll
    for (int r = 0; r < 8; r++)
        *(float4*)&gZ1[(size_t)(b0 + r) * FH + col] = acc[r];
}

// ---------------- Phase B: persistent kernel, exact stepK body per step ----------------
// 96 blocks x 256 threads, all co-resident (96 <= 148 SMs).
//   Blocks 0..31  : layer1. Block owns 16 units (64 gate-cols). Active for s < 256.
//   Blocks 32..95 : layer2. Block owns 8 units (32 gate-cols). Active for s >= 1.
// Software grid barrier between steps (release: per-writer fence + block arrive;
// acquire: single spinner with ld.acquire.gpu, then __syncthreads).
__global__ void __launch_bounds__(256, 1) lstmPersist(
    const float* __restrict__ Wh1, const float* __restrict__ Wi2,
    const float* __restrict__ Wh2, const float* __restrict__ b2)
{
    __shared__ __align__(16) float sH[1024];
    __shared__ __align__(16) float sPart[1024];
    __shared__ float sZ[64];

    const int tid = threadIdx.x;
    const int bx  = blockIdx.x;

    for (int s = 0; s < NSTEPS; s++) {
        const int rb = s & 1, wb = rb ^ 1;

        if (bx < 32) {
            // ---------- layer 1 (active s < 256) ----------
            if (s < Bv) {
                const int u0 = bx * 16;

                for (int i = tid; i < Hv; i += 256) sH[i] = ldcg(&gH1buf[rb][i]);
                __syncthreads();

                const int cg = tid & 15;
                const int ks = tid >> 4;
                const int c0 = cg * 4;
                const int g  = c0 >> 4;
                const int col = g * Hv + u0 + (c0 & 15);
                const int kb  = ks * 32;

                const float* Wp = Wh1 + (size_t)kb * FH + col;
                float4 a = make_float4(0.f, 0.f, 0.f, 0.f);
                #pragma unroll 8
                for (int j = 0; j < 32; j++) {
                    float4 w = *(const float4*)(Wp + (size_t)j * FH);
                    float hk = sH[kb + j];
                    a.x = fmaf(hk, w.x, a.x); a.y = fmaf(hk, w.y, a.y);
                    a.z = fmaf(hk, w.z, a.z); a.w = fmaf(hk, w.w, a.w);
                }
                *(float4*)&sPart[ks * 64 + c0] = a;
                __syncthreads();

                if (tid < 64) {
                    float z = 0.f;
                    #pragma unroll
                    for (int r = 0; r < 16; r++) z += sPart[r * 64 + tid];
                    const int gg = tid >> 4;
                    const int cc = gg * Hv + u0 + (tid & 15);
                    sZ[tid] = z + gZ1[(size_t)s * FH + cc];
                }
                __syncthreads();

                if (tid < 16) {
                    const int u = u0 + tid;
                    float zi = sZ[tid], zf = sZ[16 + tid], zg = sZ[32 + tid], zo = sZ[48 + tid];
                    float c = sigf(zf) * gC1[u] + sigf(zi) * tanhf(zg);
                    gC1[u] = c;
                    gH1buf[wb][u] = sigf(zo) * tanhf(c);
                    __threadfence();   // release this thread's h-write before arrive
                }
            }
        } else {
            // ---------- layer 2 (active s >= 1) ----------
            if (s >= 1) {
                const int lb = bx - 32;
                const int u0 = lb * 8;

                for (int i = tid; i < Hv; i += 256) sH[i]      = ldcg(&gH1buf[rb][i]);
                for (int i = tid; i < Hv; i += 256) sH[Hv + i] = ldcg(&gH2buf[rb][i]);
                __syncthreads();

                const int cg = tid & 7;
                const int ks = tid >> 3;
                const int c0 = cg * 4;
                const int g  = c0 >> 3;
                const int col = g * Hv + u0 + (c0 & 7);
                const int kb  = ks * 32;

                const float* Wp = (kb < Hv ? Wi2 + (size_t)kb * FH
                                           : Wh2 + (size_t)(kb - Hv) * FH) + col;
                float4 a = make_float4(0.f, 0.f, 0.f, 0.f);
                #pragma unroll 8
                for (int j = 0; j < 32; j++) {
                    float4 w = *(const float4*)(Wp + (size_t)j * FH);
                    float hk = sH[kb + j];
                    a.x = fmaf(hk, w.x, a.x); a.y = fmaf(hk, w.y, a.y);
                    a.z = fmaf(hk, w.z, a.z); a.w = fmaf(hk, w.w, a.w);
                }
                *(float4*)&sPart[ks * 32 + c0] = a;
                __syncthreads();

                if (tid < 32) {
                    float z = 0.f;
                    #pragma unroll
                    for (int r = 0; r < 32; r++) z += sPart[r * 32 + tid];
                    const int gg = tid >> 3;
                    const int cc = gg * Hv + u0 + (tid & 7);
                    sZ[tid] = z + b2[cc];
                }
                __syncthreads();

                if (tid < 8) {
                    const int u = u0 + tid;
                    float zi = sZ[tid], zf = sZ[8 + tid], zg = sZ[16 + tid], zo = sZ[24 + tid];
                    float c = sigf(zf) * gC2[u] + sigf(zi) * tanhf(zg);
                    gC2[u] = c;
                    float h = sigf(zo) * tanhf(c);
                    gH2buf[wb][u] = h;
                    gH2all[(size_t)(s - 1) * Hv + u] = h;
                    __threadfence();   // release this thread's h-write before arrive
                }
            }
        }

        // ---------- grid barrier ----------
        __syncthreads();                       // all block work (incl. fenced writes) done
        if (tid == 0) {
            atomicAdd(&g_cnt, 1);              // arrive
            const int target = GRIDB * (s + 1);
            while (ld_acq(&g_cnt) < target) { }  // acquire spin
        }
        __syncthreads();                       // release block; next step's ld.cg reads L2
    }
}

// ---------------- Phase C: out = H2all @ Wd + bd ----------------
__global__ void outK(const float* __restrict__ Wd, const float* __restrict__ bd,
                     float* __restrict__ out) {
    const int m    = blockIdx.x;
    const int o    = threadIdx.y;
    const int lane = threadIdx.x;
    const float* h = gH2all + (size_t)m * Hv;
    float acc = 0.f;
    #pragma unroll
    for (int j = 0; j < 16; j++) {
        int k = lane * 16 + j;
        acc = fmaf(h[k], __ldg(Wd + (size_t)k * 10 + o), acc);
    }
    #pragma unroll
    for (int off = 16; off; off >>= 1)
        acc += __shfl_xor_sync(0xffffffffu, acc, off);
    if (lane == 0) out[m * 10 + o] = acc + __ldg(bd + o);
}

// ---------------- launch ----------------
extern "C" void kernel_launch(void* const* d_in, const int* in_sizes, int n_in,
                              void* d_out, int out_size) {
    (void)in_sizes; (void)n_in; (void)out_size;
    const float* x   = (const float*)d_in[0];
    const float* Wi1 = (const float*)d_in[1];
    const float* Wh1 = (const float*)d_in[2];
    const float* b1  = (const float*)d_in[3];
    const float* Wi2 = (const float*)d_in[4];
    const float* Wh2 = (const float*)d_in[5];
    const float* b2  = (const float*)d_in[6];
    const float* Wd  = (const float*)d_in[7];
    const float* bd  = (const float*)d_in[8];
    float* out = (float*)d_out;

    initK<<<1, 256>>>();
    gemmZ1<<<dim3(2, 32), 256>>>(x, Wi1, b1);
    lstmPersist<<<GRIDB, 256>>>(Wh1, Wi2, Wh2, b2);
    outK<<<256, dim3(32, 10)>>>(Wd, bd, out);
}

// round 5
// speedup vs baseline: 2.1125x; 1.8971x over previous
#include <cuda_runtime.h>
#include <math.h>
#include <cstdint>

// Problem sizes
#define Bv 256
#define Tv 512
#define Fv 512
#define Hv 512
#define FH 2048
#define NSTEPS 257   // layer1 steps 0..255; layer2 pipelined (batch b = s-1) steps 1..256
#define GRIDB 96

// ---------------- device scratch (no allocations allowed) ----------------
__device__ __align__(16) float gZ1[Bv * FH];     // x[:,T-1,:] @ Wi1 + b1
__device__ __align__(16) float gH1buf[2][Hv];    // ping-pong layer1 hidden
__device__ __align__(16) float gH2buf[2][Hv];    // ping-pong layer2 hidden
__device__ __align__(16) float gH2all[Bv * Hv];  // all layer2 outputs ("last" matrix)
__device__ int g_cnt;                            // grid barrier counter (monotonic per launch)

__device__ __forceinline__ float sigf(float x) { return 1.0f / (1.0f + expf(-x)); }

__device__ __forceinline__ int ld_acq(const int* p) {
    int v;
    asm volatile("ld.acquire.gpu.global.b32 %0, [%1];" : "=r"(v) : "l"(p));
    return v;
}
__device__ __forceinline__ float ldcg(const float* p) {
    float v;
    asm volatile("ld.global.cg.f32 %0, [%1];" : "=f"(v) : "l"(p));
    return v;
}

// ---------------- init (fresh state every launch/replay) ----------------
__global__ void initK() {
    int t = threadIdx.x;
    for (int i = t; i < Hv; i += blockDim.x) {
        gH1buf[0][i] = 0.f; gH1buf[1][i] = 0.f;
        gH2buf[0][i] = 0.f; gH2buf[1][i] = 0.f;
    }
    if (t == 0) g_cnt = 0;
}

// ---------------- Phase A: Z1 = x[:,T-1,:] @ Wi1 + b1 ----------------
__global__ void gemmZ1(const float* __restrict__ x,
                       const float* __restrict__ Wi1,
                       const float* __restrict__ b1) {
    __shared__ __align__(16) float xs[8][512];
    const int tid = threadIdx.x;
    const int col = blockIdx.x * 1024 + tid * 4;
    const int b0  = blockIdx.y * 8;

    for (int i = tid; i < 8 * 512; i += 256) {
        int r = i >> 9, f = i & 511;
        xs[r][f] = x[(size_t)(b0 + r) * Tv * Fv + (size_t)(Tv - 1) * Fv + f];
    }
    __syncthreads();

    float4 acc[8];
    float4 bv = *(const float4*)(b1 + col);
    #pragma unroll
    for (int r = 0; r < 8; r++) acc[r] = bv;

    for (int k = 0; k < Fv; k++) {
        float4 w = *(const float4*)(Wi1 + (size_t)k * FH + col);
        #pragma unroll
        for (int r = 0; r < 8; r++) {
            float xv = xs[r][k];
            acc[r].x = fmaf(xv, w.x, acc[r].x);
            acc[r].y = fmaf(xv, w.y, acc[r].y);
            acc[r].z = fmaf(xv, w.z, acc[r].z);
            acc[r].w = fmaf(xv, w.w, acc[r].w);
        }
    }
    #pragma unroll
    for (int r = 0; r < 8; r++)
        *(float4*)&gZ1[(size_t)(b0 + r) * FH + col] = acc[r];
}

// ---------------- Phase B: persistent kernel (register-resident weights) ----------------
// 96 blocks x 256 threads, all co-resident.
//   Blocks 0..31  : layer1, 16 units each (64 gate-cols), active for s < 256.
//   Blocks 32..95 : layer2, 8 units each (32 gate-cols), active for s >= 1.
// Each thread holds its 32 float4 weight slice in registers; cell state lives in
// the owning thread's register. Barrier identical to the validated R4 sequence.
__global__ void __launch_bounds__(256, 1) lstmPersist(
    const float* __restrict__ Wh1, const float* __restrict__ Wi2,
    const float* __restrict__ Wh2, const float* __restrict__ b2,
    const float* __restrict__ Wd,  const float* __restrict__ bd,
    float* __restrict__ out)
{
    __shared__ __align__(16) float sH[1024];
    __shared__ __align__(16) float sPart[1024];
    __shared__ float sZ[64];

    const int tid = threadIdx.x;
    const int bx  = blockIdx.x;

    if (bx < 32) {
        // ================= layer 1 =================
        const int u0 = bx * 16;
        const int cg = tid & 15;
        const int ks = tid >> 4;
        const int c0 = cg * 4;
        const int g  = c0 >> 4;
        const int col = g * Hv + u0 + (c0 & 15);
        const int kb  = ks * 32;

        float4 rw[32];
        {
            const float* Wp = Wh1 + (size_t)kb * FH + col;
            #pragma unroll
            for (int j = 0; j < 32; j++)
                rw[j] = *(const float4*)(Wp + (size_t)j * FH);
        }
        float cst = 0.f;   // cell state for unit u0+tid (tid<16)

        for (int s = 0; s < NSTEPS; s++) {
            const int rb = s & 1, wb = rb ^ 1;
            if (s < Bv) {
                for (int i = tid; i < Hv; i += 256) sH[i] = ldcg(&gH1buf[rb][i]);
                __syncthreads();

                float4 a = make_float4(0.f, 0.f, 0.f, 0.f);
                #pragma unroll
                for (int j = 0; j < 32; j++) {
                    float hk = sH[kb + j];
                    a.x = fmaf(hk, rw[j].x, a.x); a.y = fmaf(hk, rw[j].y, a.y);
                    a.z = fmaf(hk, rw[j].z, a.z); a.w = fmaf(hk, rw[j].w, a.w);
                }
                *(float4*)&sPart[ks * 64 + c0] = a;
                __syncthreads();

                if (tid < 64) {
                    float z = 0.f;
                    #pragma unroll
                    for (int r = 0; r < 16; r++) z += sPart[r * 64 + tid];
                    const int gg = tid >> 4;
                    const int cc = gg * Hv + u0 + (tid & 15);
                    sZ[tid] = z + gZ1[(size_t)s * FH + cc];
                }
                __syncthreads();

                if (tid < 16) {
                    const int u = u0 + tid;
                    float zi = sZ[tid], zf = sZ[16 + tid], zg = sZ[32 + tid], zo = sZ[48 + tid];
                    cst = sigf(zf) * cst + sigf(zi) * tanhf(zg);
                    gH1buf[wb][u] = sigf(zo) * tanhf(cst);
                    __threadfence();
                }
            }
            __syncthreads();
            if (tid == 0) {
                atomicAdd(&g_cnt, 1);
                const int target = GRIDB * (s + 1);
                while (ld_acq(&g_cnt) < target) { }
            }
            __syncthreads();
        }
    } else {
        // ================= layer 2 =================
        const int u0 = (bx - 32) * 8;
        const int cg = tid & 7;
        const int ks = tid >> 3;
        const int c0 = cg * 4;
        const int g  = c0 >> 3;
        const int col = g * Hv + u0 + (c0 & 7);
        const int kb  = ks * 32;

        float4 rw[32];
        {
            const float* Wp = (kb < Hv ? Wi2 + (size_t)kb * FH
                                       : Wh2 + (size_t)(kb - Hv) * FH) + col;
            #pragma unroll
            for (int j = 0; j < 32; j++)
                rw[j] = *(const float4*)(Wp + (size_t)j * FH);
        }
        float b2r = 0.f;
        if (tid < 32) {
            const int gg = tid >> 3;
            b2r = b2[gg * Hv + u0 + (tid & 7)];
        }
        float cst = 0.f;   // cell state for unit u0+tid (tid<8)

        for (int s = 0; s < NSTEPS; s++) {
            const int rb = s & 1, wb = rb ^ 1;
            if (s >= 1) {
                for (int i = tid; i < Hv; i += 256) sH[i]      = ldcg(&gH1buf[rb][i]);
                for (int i = tid; i < Hv; i += 256) sH[Hv + i] = ldcg(&gH2buf[rb][i]);
                __syncthreads();

                float4 a = make_float4(0.f, 0.f, 0.f, 0.f);
                #pragma unroll
                for (int j = 0; j < 32; j++) {
                    float hk = sH[kb + j];
                    a.x = fmaf(hk, rw[j].x, a.x); a.y = fmaf(hk, rw[j].y, a.y);
                    a.z = fmaf(hk, rw[j].z, a.z); a.w = fmaf(hk, rw[j].w, a.w);
                }
                *(float4*)&sPart[ks * 32 + c0] = a;
                __syncthreads();

                if (tid < 32) {
                    float z = 0.f;
                    #pragma unroll
                    for (int r = 0; r < 32; r++) z += sPart[r * 32 + tid];
                    sZ[tid] = z + b2r;
                }
                __syncthreads();

                if (tid < 8) {
                    const int u = u0 + tid;
                    float zi = sZ[tid], zf = sZ[8 + tid], zg = sZ[16 + tid], zo = sZ[24 + tid];
                    cst = sigf(zf) * cst + sigf(zi) * tanhf(zg);
                    float h = sigf(zo) * tanhf(cst);
                    gH2buf[wb][u] = h;
                    gH2all[(size_t)(s - 1) * Hv + u] = h;
                    __threadfence();
                }
            }
            __syncthreads();
            if (tid == 0) {
                atomicAdd(&g_cnt, 1);
                const int target = GRIDB * (s + 1);
                while (ld_acq(&g_cnt) < target) { }
            }
            __syncthreads();
        }
    }

    // ================= fused output GEMM: out = gH2all @ Wd + bd =================
    // Final barrier above guarantees gH2all complete & visible (ld.cg reads L2).
    const int w    = tid >> 5;
    const int lane = tid & 31;
    for (int m = bx; m < Bv; m += GRIDB) {
        for (int o = w; o < 10; o += 8) {
            float acc = 0.f;
            #pragma unroll
            for (int j = 0; j < 16; j++) {
                int k = lane * 16 + j;
                acc = fmaf(ldcg(&gH2all[(size_t)m * Hv + k]), __ldg(Wd + (size_t)k * 10 + o), acc);
            }
            #pragma unroll
            for (int off = 16; off; off >>= 1)
                acc += __shfl_xor_sync(0xffffffffu, acc, off);
            if (lane == 0) out[m * 10 + o] = acc + __ldg(bd + o);
        }
    }
}

// ---------------- launch ----------------
extern "C" void kernel_launch(void* const* d_in, const int* in_sizes, int n_in,
                              void* d_out, int out_size) {
    (void)in_sizes; (void)n_in; (void)out_size;
    const float* x   = (const float*)d_in[0];
    const float* Wi1 = (const float*)d_in[1];
    const float* Wh1 = (const float*)d_in[2];
    const float* b1  = (const float*)d_in[3];
    const float* Wi2 = (const float*)d_in[4];
    const float* Wh2 = (const float*)d_in[5];
    const float* b2  = (const float*)d_in[6];
    const float* Wd  = (const float*)d_in[7];
    const float* bd  = (const float*)d_in[8];
    float* out = (float*)d_out;

    initK<<<1, 256>>>();
    gemmZ1<<<dim3(2, 32), 256>>>(x, Wi1, b1);
    lstmPersist<<<GRIDB, 256>>>(Wh1, Wi2, Wh2, b2, Wd, bd, out);
}